// round 1
// baseline (speedup 1.0000x reference)
#include <cuda_runtime.h>
#include <cstdint>

// SpecialSpmmFinal: out[src[e], :] += edge_w[e, :] for e in [0, E)
// N=100000, E=3200000, F=16, fp32. src = edge[0] (first E ints of the
// [2, E] edge tensor).

#define N_NODES 100000
#define N_EDGES 3200000
#define FEAT 16

// ---------------------------------------------------------------------------
// Zero the output (harness poisons d_out with 0xAA).
// 100000*16 floats = 1.6M floats = 400k float4.
// ---------------------------------------------------------------------------
__global__ void zero_out_kernel(float4* __restrict__ out, int n4) {
    int i = blockIdx.x * blockDim.x + threadIdx.x;
    if (i < n4) out[i] = make_float4(0.f, 0.f, 0.f, 0.f);
}

// ---------------------------------------------------------------------------
// Scatter-add: one thread per edge. Each thread reads its 64-byte row as
// 4x float4 and issues 4x red.global.add.v4.f32 (no-return vector reduction,
// sm_90+). Atomic destinations are L2-resident (out = 6.4 MB << 126 MB L2).
// ---------------------------------------------------------------------------
__global__ void __launch_bounds__(256)
scatter_add_kernel(const int* __restrict__ src,
                   const float4* __restrict__ w,   // [E, 4] float4 view of [E,16] f32
                   float* __restrict__ out) {      // [N, 16] f32
    int e = blockIdx.x * blockDim.x + threadIdx.x;
    if (e >= N_EDGES) return;

    int s = src[e];
    const float4* row = w + (size_t)e * 4;
    float* dst = out + (size_t)s * FEAT;

    #pragma unroll
    for (int j = 0; j < 4; ++j) {
        float4 v = row[j];
        asm volatile(
            "red.global.add.v4.f32 [%0], {%1, %2, %3, %4};"
            :: "l"(dst + j * 4), "f"(v.x), "f"(v.y), "f"(v.z), "f"(v.w)
            : "memory");
    }
}

// ---------------------------------------------------------------------------
// kernel_launch
// Inputs (metadata order): edge [2,E] int32, edge_w [E,16] f32, N, E,
// out_features (scalars, unused — constants above).
// ---------------------------------------------------------------------------
extern "C" void kernel_launch(void* const* d_in, const int* in_sizes, int n_in,
                              void* d_out, int out_size) {
    const int*    edge   = (const int*)d_in[0];     // [2, E]; src = edge[0..E)
    const float4* edge_w = (const float4*)d_in[1];  // [E, 16] f32 = [E, 4] float4
    float*        out    = (float*)d_out;           // [N, 16] f32

    (void)in_sizes; (void)n_in; (void)out_size;

    // 1) zero output
    {
        int n4 = N_NODES * FEAT / 4;               // 400000
        int threads = 256;
        int blocks = (n4 + threads - 1) / threads;
        zero_out_kernel<<<blocks, threads>>>((float4*)out, n4);
    }

    // 2) scatter add
    {
        int threads = 256;
        int blocks = (N_EDGES + threads - 1) / threads;  // 12500
        scatter_add_kernel<<<blocks, threads>>>(edge, edge_w, out);
    }
}